// round 13
// baseline (speedup 1.0000x reference)
#include <cuda_runtime.h>
#include <cuda_fp16.h>
#include <cstdint>

// Problem constants (fixed by the dataset)
constexpr int BB   = 16;     // batch
constexpr int NTOK = 16384;  // tokens
constexpr int DD   = 64;     // model dim (= dhf)
constexpr int GG   = 256;    // groups
constexpr int CC   = 64;     // tokens per group
constexpr int NH   = 4;      // heads
// SCALE = 4.0 multiplies scores; folded into Q at fp16 staging (exact: power of two)

#define PADH 72   // half smem row stride (144 B, ldmatrix conflict-free)
#define LDSF 68   // fp32 smem row stride (stash / stage)

// intra smem layout (half indices); fp32 stage after the fp16 region
#define XH_OFF 0
#define QH_OFF 4608
#define KH_OFF 9216
#define VH_OFF 13824
#define STAGE_HOFF 18432                   // fp32 stage at byte 36864
#define SMEM_INTRA_BYTES (36864 + 17408)   // 54272 B -> 3 blocks/SM

// inter-attn smem layout (half indices)
#define PI_OFF  0
#define KI_OFF  18432
#define VI_OFF  36864
#define QI_OFF  55296
#define SMEM_IATT_BYTES ((55296 + 4608) * 2)   // 119808 B

// ---------------- scratch (no allocations allowed) ----------------
__device__ float  g_pooled[BB * GG * DD];          // 1 MiB
__device__ float  g_inter[BB * GG * DD];           // 1 MiB
__device__ __half g_intra[BB * GG * CC * DD];      // 32 MiB (fp16 intra result)
// pre-packed fp16 weight fragments: [mat][(ntg*4+kt)*64 + 2*lane + j]
// mats: 0=Wq_a 1=Wk_a 2=Wv_a 3=Wo_a 4=Wq_i 5=Wk_i 6=Wv_i 7=Wo_i
__device__ uint32_t g_wfrag[8][2048];              // 64 KiB

// ---------------- mma / ldmatrix / cp.async helpers ----------------
__device__ __forceinline__ void ldsm_x4(uint32_t& r0, uint32_t& r1, uint32_t& r2, uint32_t& r3, uint32_t a) {
    asm volatile("ldmatrix.sync.aligned.m8n8.x4.shared.b16 {%0,%1,%2,%3}, [%4];"
        : "=r"(r0), "=r"(r1), "=r"(r2), "=r"(r3) : "r"(a));
}
__device__ __forceinline__ void ldsm_x4t(uint32_t& r0, uint32_t& r1, uint32_t& r2, uint32_t& r3, uint32_t a) {
    asm volatile("ldmatrix.sync.aligned.m8n8.x4.trans.shared.b16 {%0,%1,%2,%3}, [%4];"
        : "=r"(r0), "=r"(r1), "=r"(r2), "=r"(r3) : "r"(a));
}
__device__ __forceinline__ void mma16(float c[4],
    uint32_t a0, uint32_t a1, uint32_t a2, uint32_t a3, uint32_t b0, uint32_t b1) {
    asm volatile("mma.sync.aligned.m16n8k16.row.col.f32.f16.f16.f32 "
        "{%0,%1,%2,%3}, {%4,%5,%6,%7}, {%8,%9}, {%0,%1,%2,%3};"
        : "+f"(c[0]), "+f"(c[1]), "+f"(c[2]), "+f"(c[3])
        : "r"(a0), "r"(a1), "r"(a2), "r"(a3), "r"(b0), "r"(b1));
}
__device__ __forceinline__ uint32_t packh2(float a, float b) {
    uint32_t u;
    asm("cvt.rn.f16x2.f32 %0, %1, %2;" : "=r"(u) : "f"(b), "f"(a));
    return u;
}
__device__ __forceinline__ void cp_async16(uint32_t dst, const void* src) {
    asm volatile("cp.async.ca.shared.global [%0], [%1], 16;" :: "r"(dst), "l"(src));
}
__device__ __forceinline__ void cp_commit() { asm volatile("cp.async.commit_group;" ::: "memory"); }
__device__ __forceinline__ void cp_wait0()  { asm volatile("cp.async.wait_group 0;" ::: "memory"); }

// ---------------- Kernel 0: pack weights into B-fragment layout ----------------
__global__ __launch_bounds__(256) void prep_w_kernel(
    const float* __restrict__ Wqa, const float* __restrict__ Wka,
    const float* __restrict__ Wva, const float* __restrict__ Woa,
    const float* __restrict__ Wqi, const float* __restrict__ Wki,
    const float* __restrict__ Wvi, const float* __restrict__ Woi)
{
    const int idx = blockIdx.x * 256 + threadIdx.x;   // 0..16383
    const int mat = idx >> 11;
    const int t   = idx & 2047;
    const int lane2 = t & 63;        // 2*lane + j
    const int j = lane2 & 1, l = lane2 >> 1;
    const int tile = t >> 6;         // ntg*4 + kt
    const int kt = tile & 3, ntg = tile >> 2;
    const float* W =
        (mat == 0) ? Wqa : (mat == 1) ? Wka : (mat == 2) ? Wva : (mat == 3) ? Woa :
        (mat == 4) ? Wqi : (mat == 5) ? Wki : (mat == 6) ? Wvi : Woi;
    const int row = 8 * ntg + (l >> 2);
    const int col = 16 * kt + 8 * j + 2 * (l & 3);
    g_wfrag[mat][t] = packh2(W[row * 64 + col], W[row * 64 + col + 1]);
}

// ---------------- Kernel 1: intra MHA, 2 groups per block, cp.async pipelined ----------------
// grid = 2048 (b*128 + gpair), 256 threads = 8 warps, dyn smem = 54272 B
__global__ __launch_bounds__(256, 3) void intra_kernel(
    const float* __restrict__ x, const int* __restrict__ part,
    const float* __restrict__ bq, const float* __restrict__ bk,
    const float* __restrict__ bv, const float* __restrict__ bo)
{
    extern __shared__ __half hsm[];
    float* stage = (float*)(hsm + STAGE_HOFF);   // 64 x LDSF fp32
    float* stash = (float*)(hsm + QH_OFF);       // 64 x LDSF fp32 overlay (dead Q/K)
    float* tmp   = (float*)(hsm + VH_OFF);       // 256 fp32 overlay (dead V)

    const int tid = threadIdx.x;
    const int bb = blockIdx.x >> 7;
    const int gp = blockIdx.x & 127;
    const float* xb = x + (size_t)bb * NTOK * DD;

    const int lane = tid & 31, w = tid >> 5;
    const int mt = w & 3, nq = w >> 2;
    const int r  = lane >> 2, cc = lane & 3;
    const int ln = lane & 7, sel = lane >> 3;
    const int offA   = (ln + 8 * (sel & 1)) * PADH + 8 * (sel >> 1);           // A x4
    const int offBK  = (ln + 8 * (sel >> 1)) * PADH + 8 * (sel & 1);           // B x4 (2 n-tiles, k16)
    const int offB4t = (lane & 15) * PADH + 8 * (lane >> 4);                   // B x4 trans (2 n-halves)
    const uint32_t sbase = (uint32_t)__cvta_generic_to_shared(hsm);
    const uint32_t stage_sb = sbase + STAGE_HOFF * 2;
    const int row0 = 16 * mt + r;

    auto issue_gather = [&](int g) {
        const int* pg = part + (size_t)g * CC;
#pragma unroll
        for (int k = 0; k < 4; ++k) {
            int f = tid + 256 * k;
            int row = f >> 4, c4 = f & 15;
            int tok = pg[row];
            cp_async16(stage_sb + (row * LDSF + 4 * c4) * 4, xb + (size_t)tok * DD + 4 * c4);
        }
        cp_commit();
    };
    auto convert_x = [&]() {
#pragma unroll
        for (int k = 0; k < 4; ++k) {
            int f = tid + 256 * k;
            int row = f >> 4, c4 = f & 15;
            float4 v = *(float4*)&stage[row * LDSF + 4 * c4];
            __half* d = hsm + XH_OFF + row * PADH + 4 * c4;
            *(half2*)(d)     = __floats2half2_rn(v.x, v.y);
            *(half2*)(d + 2) = __floats2half2_rn(v.z, v.w);
        }
    };

    auto compute_group = [&](int g) {
        // ---- A fragments of xs: shared by Q, K, V projections ----
        uint32_t xa[4][4];
#pragma unroll
        for (int kt = 0; kt < 4; ++kt)
            ldsm_x4(xa[kt][0], xa[kt][1], xa[kt][2], xa[kt][3],
                    sbase + 2 * (XH_OFF + 16 * mt * PADH + 16 * kt + offA));

        auto projG = [&](int mat, const float* __restrict__ bias, int Doff, float scl) {
            const uint2* wf = (const uint2*)g_wfrag[mat];
            float acc[4][4] = {};
#pragma unroll
            for (int nt = 0; nt < 4; ++nt) {
                const int ntg = 4 * nq + nt;
#pragma unroll
                for (int kt = 0; kt < 4; ++kt) {
                    uint2 f = wf[(ntg * 4 + kt) * 32 + lane];
                    mma16(acc[nt], xa[kt][0], xa[kt][1], xa[kt][2], xa[kt][3], f.x, f.y);
                }
            }
#pragma unroll
            for (int nt = 0; nt < 4; ++nt) {
                const int n0 = 32 * nq + 8 * nt;
                float b0v = bias[n0 + 2 * cc], b1v = bias[n0 + 2 * cc + 1];
                *(half2*)(hsm + Doff + row0 * PADH + n0 + 2 * cc) =
                    __floats2half2_rn((acc[nt][0] + b0v) * scl, (acc[nt][1] + b1v) * scl);
                *(half2*)(hsm + Doff + (row0 + 8) * PADH + n0 + 2 * cc) =
                    __floats2half2_rn((acc[nt][2] + b0v) * scl, (acc[nt][3] + b1v) * scl);
            }
        };

        projG(0, bq, QH_OFF, 4.0f);
        projG(1, bk, KH_OFF, 1.0f);
        projG(2, bv, VH_OFF, 1.0f);
        __syncthreads();

        // ---- attention, register-resident ----
        {
            const int hsel = w >> 2;
            const int arow = 16 * mt;
#pragma unroll
            for (int hp = 0; hp < 2; ++hp) {
                const int h = 2 * hp + hsel;
                const int hq = 16 * h;
                uint32_t a0, a1, a2, a3;
                ldsm_x4(a0, a1, a2, a3, sbase + 2 * (QH_OFF + arow * PADH + hq + offA));
                float s[8][4];
#pragma unroll
                for (int ntp = 0; ntp < 4; ++ntp) {
                    uint32_t b0, b1, b2, b3;
                    ldsm_x4(b0, b1, b2, b3, sbase + 2 * (KH_OFF + 16 * ntp * PADH + hq + offBK));
                    s[2*ntp][0] = s[2*ntp][1] = s[2*ntp][2] = s[2*ntp][3] = 0.f;
                    s[2*ntp+1][0] = s[2*ntp+1][1] = s[2*ntp+1][2] = s[2*ntp+1][3] = 0.f;
                    mma16(s[2*ntp],     a0, a1, a2, a3, b0, b1);
                    mma16(s[2*ntp+1],   a0, a1, a2, a3, b2, b3);
                }
                float mx0 = -1e30f, mx1 = -1e30f;
#pragma unroll
                for (int nt = 0; nt < 8; ++nt) {
                    mx0 = fmaxf(mx0, fmaxf(s[nt][0], s[nt][1]));
                    mx1 = fmaxf(mx1, fmaxf(s[nt][2], s[nt][3]));
                }
                mx0 = fmaxf(mx0, __shfl_xor_sync(0xffffffffu, mx0, 1));
                mx0 = fmaxf(mx0, __shfl_xor_sync(0xffffffffu, mx0, 2));
                mx1 = fmaxf(mx1, __shfl_xor_sync(0xffffffffu, mx1, 1));
                mx1 = fmaxf(mx1, __shfl_xor_sync(0xffffffffu, mx1, 2));
                float sum0 = 0.f, sum1 = 0.f;
#pragma unroll
                for (int nt = 0; nt < 8; ++nt) {
                    s[nt][0] = __expf(s[nt][0] - mx0); sum0 += s[nt][0];
                    s[nt][1] = __expf(s[nt][1] - mx0); sum0 += s[nt][1];
                    s[nt][2] = __expf(s[nt][2] - mx1); sum1 += s[nt][2];
                    s[nt][3] = __expf(s[nt][3] - mx1); sum1 += s[nt][3];
                }
                sum0 += __shfl_xor_sync(0xffffffffu, sum0, 1);
                sum0 += __shfl_xor_sync(0xffffffffu, sum0, 2);
                sum1 += __shfl_xor_sync(0xffffffffu, sum1, 1);
                sum1 += __shfl_xor_sync(0xffffffffu, sum1, 2);
                const float inv0 = 1.f / sum0, inv1 = 1.f / sum1;
                float o[2][4] = {};
#pragma unroll
                for (int kc = 0; kc < 4; ++kc) {
                    uint32_t pa0 = packh2(s[2*kc][0] * inv0, s[2*kc][1] * inv0);
                    uint32_t pa1 = packh2(s[2*kc][2] * inv1, s[2*kc][3] * inv1);
                    uint32_t pa2 = packh2(s[2*kc+1][0] * inv0, s[2*kc+1][1] * inv0);
                    uint32_t pa3 = packh2(s[2*kc+1][2] * inv1, s[2*kc+1][3] * inv1);
                    uint32_t b0, b1, b2, b3;
                    ldsm_x4t(b0, b1, b2, b3, sbase + 2 * (VH_OFF + 16 * kc * PADH + hq + offB4t));
                    mma16(o[0], pa0, pa1, pa2, pa3, b0, b1);
                    mma16(o[1], pa0, pa1, pa2, pa3, b2, b3);
                }
#pragma unroll
                for (int nt2 = 0; nt2 < 2; ++nt2) {
                    const int n0 = hq + 8 * nt2 + 2 * cc;
                    *(half2*)(hsm + XH_OFF + (arow + r) * PADH + n0) =
                        __floats2half2_rn(o[nt2][0], o[nt2][1]);
                    *(half2*)(hsm + XH_OFF + (arow + r + 8) * PADH + n0) =
                        __floats2half2_rn(o[nt2][2], o[nt2][3]);
                }
            }
        }
        __syncthreads();

        // ---- O projection (+bias) -> fp16 g_intra + fp32 stash ----
        {
#pragma unroll
            for (int kt = 0; kt < 4; ++kt)
                ldsm_x4(xa[kt][0], xa[kt][1], xa[kt][2], xa[kt][3],
                        sbase + 2 * (XH_OFF + 16 * mt * PADH + 16 * kt + offA));
            const uint2* wf = (const uint2*)g_wfrag[3];
            float acc[4][4] = {};
#pragma unroll
            for (int nt = 0; nt < 4; ++nt) {
                const int ntg = 4 * nq + nt;
#pragma unroll
                for (int kt = 0; kt < 4; ++kt) {
                    uint2 f = wf[(ntg * 4 + kt) * 32 + lane];
                    mma16(acc[nt], xa[kt][0], xa[kt][1], xa[kt][2], xa[kt][3], f.x, f.y);
                }
            }
            __half* dI = g_intra + ((size_t)(bb * GG + g) * CC) * DD;
#pragma unroll
            for (int nt = 0; nt < 4; ++nt) {
                const int n0 = 32 * nq + 8 * nt;
                float b0v = bo[n0 + 2 * cc], b1v = bo[n0 + 2 * cc + 1];
                float v0 = acc[nt][0] + b0v, v1 = acc[nt][1] + b1v;
                float v2 = acc[nt][2] + b0v, v3 = acc[nt][3] + b1v;
                *(half2*)(dI + row0 * DD + n0 + 2 * cc)       = __floats2half2_rn(v0, v1);
                *(half2*)(dI + (row0 + 8) * DD + n0 + 2 * cc) = __floats2half2_rn(v2, v3);
                *(float2*)&stash[row0 * LDSF + n0 + 2 * cc]       = make_float2(v0, v1);
                *(float2*)&stash[(row0 + 8) * LDSF + n0 + 2 * cc] = make_float2(v2, v3);
            }
        }
        __syncthreads();

        // ---- pooled max (256 threads: 4 quarters x 64 cols) ----
        {
            const int col = tid & 63, q = tid >> 6;
            const float* sp = stash + (16 * q) * LDSF + col;
            float m = sp[0];
#pragma unroll
            for (int i = 1; i < 16; ++i) m = fmaxf(m, sp[i * LDSF]);
            tmp[(q << 6) + col] = m;
        }
        __syncthreads();
        if (tid < 64) {
            float m = fmaxf(fmaxf(tmp[tid], tmp[64 + tid]),
                            fmaxf(tmp[128 + tid], tmp[192 + tid]));
            g_pooled[((size_t)bb * GG + g) * DD + tid] = m;
        }
    };

    // ---- pipelined 2-group flow ----
    const int gA = 2 * gp, gB = 2 * gp + 1;
    issue_gather(gA);
    cp_wait0();
    convert_x();          // each thread reads exactly the slots it copied
    issue_gather(gB);     // same-thread slot reuse: program order makes this safe
    __syncthreads();
    compute_group(gA);
    cp_wait0();
    __syncthreads();      // all threads past pooled-max reads before xs overwrite
    convert_x();
    __syncthreads();
    compute_group(gB);
}

// ---------------- Kernel 2: fused inter QKV + flash attention + O-proj ----------------
// grid = 64 (b = blk>>2, qchunk = blk&3), 256 threads, dyn smem = 119808 B
__global__ __launch_bounds__(256) void inter_attn_mma(
    const float* __restrict__ bq, const float* __restrict__ bk,
    const float* __restrict__ bv, const float* __restrict__ bo)
{
    extern __shared__ __half hsm[];
    const int tid = threadIdx.x;
    const int b  = blockIdx.x >> 2;
    const int qc = blockIdx.x & 3;

    const int lane = tid & 31, w = tid >> 5;
    const int mt = w & 3, nq = w >> 2;
    const int r  = lane >> 2, cc = lane & 3;
    const int ln = lane & 7, sel = lane >> 3;
    const int offA   = (ln + 8 * (sel & 1)) * PADH + 8 * (sel >> 1);
    const int offBK  = (ln + 8 * (sel >> 1)) * PADH + 8 * (sel & 1);
    const int offB4t = (lane & 15) * PADH + 8 * (lane >> 4);
    const uint32_t sbase = (uint32_t)__cvta_generic_to_shared(hsm);

    const float* pb = g_pooled + (size_t)b * GG * DD;

    // ---- stage pooled (256 x 64) as fp16 ----
#pragma unroll
    for (int k = 0; k < 16; ++k) {
        int f = tid + 256 * k;
        int row = f >> 4, c4 = f & 15;
        float4 v = ((const float4*)(pb + row * 64))[c4];
        __half* d = hsm + PI_OFF + row * PADH + 4 * c4;
        *(half2*)(d)     = __floats2half2_rn(v.x, v.y);
        *(half2*)(d + 2) = __floats2half2_rn(v.z, v.w);
    }
    __syncthreads();

    // ---- K, V projections over all 256 rows; Q over own 64 rows ----
    {
        const uint2* wfK = (const uint2*)g_wfrag[5];
        const uint2* wfV = (const uint2*)g_wfrag[6];
#pragma unroll
        for (int hf = 0; hf < 2; ++hf) {
            const int rt = w + 8 * hf;
            uint32_t pa[4][4];
#pragma unroll
            for (int kt = 0; kt < 4; ++kt)
                ldsm_x4(pa[kt][0], pa[kt][1], pa[kt][2], pa[kt][3],
                        sbase + 2 * (PI_OFF + 16 * rt * PADH + 16 * kt + offA));
            const int rr0 = 16 * rt + r;
#pragma unroll
            for (int ng = 0; ng < 8; ++ng) {
                float ak[4] = {}, av[4] = {};
#pragma unroll
                for (int kt = 0; kt < 4; ++kt) {
                    uint2 fk = wfK[(ng * 4 + kt) * 32 + lane];
                    uint2 fv = wfV[(ng * 4 + kt) * 32 + lane];
                    mma16(ak, pa[kt][0], pa[kt][1], pa[kt][2], pa[kt][3], fk.x, fk.y);
                    mma16(av, pa[kt][0], pa[kt][1], pa[kt][2], pa[kt][3], fv.x, fv.y);
                }
                const int n0 = 8 * ng;
                float bk0 = bk[n0 + 2 * cc], bk1 = bk[n0 + 2 * cc + 1];
                float bv0 = bv[n0 + 2 * cc], bv1 = bv[n0 + 2 * cc + 1];
                *(half2*)(hsm + KI_OFF + rr0 * PADH + n0 + 2 * cc) =
                    __floats2half2_rn(ak[0] + bk0, ak[1] + bk1);
                *(half2*)(hsm + KI_OFF + (rr0 + 8) * PADH + n0 + 2 * cc) =
                    __floats2half2_rn(ak[2] + bk0, ak[3] + bk1);
                *(half2*)(hsm + VI_OFF + rr0 * PADH + n0 + 2 * cc) =
                    __floats2half2_rn(av[0] + bv0, av[1] + bv1);
                *(half2*)(hsm + VI_OFF + (rr0 + 8) * PADH + n0 + 2 * cc) =
                    __floats2half2_rn(av[2] + bv0, av[3] + bv1);
            }
        }
        const uint2* wfQ = (const uint2*)g_wfrag[4];
        const int qt = 4 * qc + mt;
        uint32_t pa[4][4];
#pragma unroll
        for (int kt = 0; kt < 4; ++kt)
            ldsm_x4(pa[kt][0], pa[kt][1], pa[kt][2], pa[kt][3],
                    sbase + 2 * (PI_OFF + 16 * qt * PADH + 16 * kt + offA));
        float acc[4][4] = {};
#pragma unroll
        for (int nt = 0; nt < 4; ++nt) {
            const int ntg = 4 * nq + nt;
#pragma unroll
            for (int kt = 0; kt < 4; ++kt) {
                uint2 f = wfQ[(ntg * 4 + kt) * 32 + lane];
                mma16(acc[nt], pa[kt][0], pa[kt][1], pa[kt][2], pa[kt][3], f.x, f.y);
            }
        }
        const int lrow0 = 16 * mt + r;
#pragma unroll
        for (int nt = 0; nt < 4; ++nt) {
            const int n0 = 32 * nq + 8 * nt;
            float b0v = bq[n0 + 2 * cc], b1v = bq[n0 + 2 * cc + 1];
            *(half2*)(hsm + QI_OFF + lrow0 * PADH + n0 + 2 * cc) =
                __floats2half2_rn((acc[nt][0] + b0v) * 4.f, (acc[nt][1] + b1v) * 4.f);
            *(half2*)(hsm + QI_OFF + (lrow0 + 8) * PADH + n0 + 2 * cc) =
                __floats2half2_rn((acc[nt][2] + b0v) * 4.f, (acc[nt][3] + b1v) * 4.f);
        }
    }
    __syncthreads();

    // ---- flash attention: warp = (mt rows, hsel head-pair), 256 keys in 2 chunks ----
    {
        const int hsel = w >> 2;
        const int arow = 16 * mt;
#pragma unroll 1
        for (int hp = 0; hp < 2; ++hp) {
            const int h = 2 * hp + hsel;
            const int hq = 16 * h;
            uint32_t a0, a1, a2, a3;
            ldsm_x4(a0, a1, a2, a3, sbase + 2 * (QI_OFF + arow * PADH + hq + offA));
            float o[2][4] = {};
            float m0 = -1e30f, m1 = -1e30f, l0 = 0.f, l1 = 0.f;
#pragma unroll 1
            for (int c = 0; c < 2; ++c) {
                float s[16][4];
#pragma unroll
                for (int ntp = 0; ntp < 8; ++ntp) {
                    uint32_t b0, b1, b2, b3;
                    ldsm_x4(b0, b1, b2, b3,
                        sbase + 2 * (KI_OFF + (128 * c + 16 * ntp) * PADH + hq + offBK));
                    s[2*ntp][0] = s[2*ntp][1] = s[2*ntp][2] = s[2*ntp][3] = 0.f;
                    s[2*ntp+1][0] = s[2*ntp+1][1] = s[2*ntp+1][2] = s[2*ntp+1][3] = 0.f;
                    mma16(s[2*ntp],   a0, a1, a2, a3, b0, b1);
                    mma16(s[2*ntp+1], a0, a1, a2, a3, b2, b3);
                }
                float cm0 = -1e30f, cm1 = -1e30f;
#pragma unroll
                for (int nt = 0; nt < 16; ++nt) {
                    cm0 = fmaxf(cm0, fmaxf(s[nt][0], s[nt][1]));
                    cm1 = fmaxf(cm1, fmaxf(s[nt][2], s[nt][3]));
                }
                cm0 = fmaxf(cm0, __shfl_xor_sync(0xffffffffu, cm0, 1));
                cm0 = fmaxf(cm0, __shfl_xor_sync(0xffffffffu, cm0, 2));
                cm1 = fmaxf(cm1, __shfl_xor_sync(0xffffffffu, cm1, 1));
                cm1 = fmaxf(cm1, __shfl_xor_sync(0xffffffffu, cm1, 2));
                float nm0 = fmaxf(m0, cm0), nm1 = fmaxf(m1, cm1);
                float sc0 = __expf(m0 - nm0), sc1 = __expf(m1 - nm1);
                l0 *= sc0; l1 *= sc1;
#pragma unroll
                for (int nt2 = 0; nt2 < 2; ++nt2) {
                    o[nt2][0] *= sc0; o[nt2][1] *= sc0;
                    o[nt2][2] *= sc1; o[nt2][3] *= sc1;
                }
                float cl0 = 0.f, cl1 = 0.f;
#pragma unroll
                for (int nt = 0; nt < 16; ++nt) {
                    s[nt][0] = __expf(s[nt][0] - nm0); cl0 += s[nt][0];
                    s[nt][1] = __expf(s[nt][1] - nm0); cl0 += s[nt][1];
                    s[nt][2] = __expf(s[nt][2] - nm1); cl1 += s[nt][2];
                    s[nt][3] = __expf(s[nt][3] - nm1); cl1 += s[nt][3];
                }
                cl0 += __shfl_xor_sync(0xffffffffu, cl0, 1);
                cl0 += __shfl_xor_sync(0xffffffffu, cl0, 2);
                cl1 += __shfl_xor_sync(0xffffffffu, cl1, 1);
                cl1 += __shfl_xor_sync(0xffffffffu, cl1, 2);
                l0 += cl0; l1 += cl1;
                m0 = nm0; m1 = nm1;
#pragma unroll
                for (int kc = 0; kc < 8; ++kc) {
                    uint32_t pa0 = packh2(s[2*kc][0], s[2*kc][1]);
                    uint32_t pa1 = packh2(s[2*kc][2], s[2*kc][3]);
                    uint32_t pa2 = packh2(s[2*kc+1][0], s[2*kc+1][1]);
                    uint32_t pa3 = packh2(s[2*kc+1][2], s[2*kc+1][3]);
                    uint32_t b0, b1, b2, b3;
                    ldsm_x4t(b0, b1, b2, b3,
                        sbase + 2 * (VI_OFF + (128 * c + 16 * kc) * PADH + hq + offB4t));
                    mma16(o[0], pa0, pa1, pa2, pa3, b0, b1);
                    mma16(o[1], pa0, pa1, pa2, pa3, b2, b3);
                }
            }
            const float inv0 = 1.f / l0, inv1 = 1.f / l1;
#pragma unroll
            for (int nt2 = 0; nt2 < 2; ++nt2) {
                const int n0 = hq + 8 * nt2 + 2 * cc;
                *(half2*)(hsm + QI_OFF + (arow + r) * PADH + n0) =
                    __floats2half2_rn(o[nt2][0] * inv0, o[nt2][1] * inv0);
                *(half2*)(hsm + QI_OFF + (arow + r + 8) * PADH + n0) =
                    __floats2half2_rn(o[nt2][2] * inv1, o[nt2][3] * inv1);
            }
        }
    }
    __syncthreads();

    // ---- O projection (+bias) -> g_inter ----
    {
        uint32_t xa[4][4];
#pragma unroll
        for (int kt = 0; kt < 4; ++kt)
            ldsm_x4(xa[kt][0], xa[kt][1], xa[kt][2], xa[kt][3],
                    sbase + 2 * (QI_OFF + 16 * mt * PADH + 16 * kt + offA));
        const uint2* wf = (const uint2*)g_wfrag[7];
        float acc[4][4] = {};
#pragma unroll
        for (int nt = 0; nt < 4; ++nt) {
            const int ntg = 4 * nq + nt;
#pragma unroll
            for (int kt = 0; kt < 4; ++kt) {
                uint2 f = wf[(ntg * 4 + kt) * 32 + lane];
                mma16(acc[nt], xa[kt][0], xa[kt][1], xa[kt][2], xa[kt][3], f.x, f.y);
            }
        }
        const int row0 = 16 * mt + r;
        float* dst = g_inter + ((size_t)b * GG + qc * 64) * DD;
#pragma unroll
        for (int nt = 0; nt < 4; ++nt) {
            const int n0 = 32 * nq + 8 * nt;
            float b0v = bo[n0 + 2 * cc], b1v = bo[n0 + 2 * cc + 1];
            *(float2*)(dst + row0 * DD + n0 + 2 * cc) =
                make_float2(acc[nt][0] + b0v, acc[nt][1] + b1v);
            *(float2*)(dst + (row0 + 8) * DD + n0 + 2 * cc) =
                make_float2(acc[nt][2] + b0v, acc[nt][3] + b1v);
        }
    }
}

// ---------------- Kernel 3: final add + scatter (only writer of out) ----------------
__global__ __launch_bounds__(256) void final_scatter_kernel(
    const int* __restrict__ part, float* __restrict__ out)
{
    __shared__ __align__(16) float iv[64];
    __shared__ int toks[64];
    const int tid = threadIdx.x;
    const int b = blockIdx.x >> 8;
    const int g = blockIdx.x & 255;
    if (tid < 64) iv[tid] = g_inter[((size_t)b * GG + g) * DD + tid];
    else if (tid < 128) toks[tid - 64] = part[(size_t)g * CC + (tid - 64)];
    __syncthreads();
    const __half* src = g_intra + ((size_t)(b * GG + g) * CC) * DD;
#pragma unroll
    for (int k = 0; k < 4; ++k) {
        int f = tid + 256 * k;
        int row = f >> 4, c4 = f & 15;
        half2 h0 = *(const half2*)(src + row * DD + 4 * c4);
        half2 h1 = *(const half2*)(src + row * DD + 4 * c4 + 2);
        float4 a = *(const float4*)&iv[4 * c4];
        float2 f0 = __half22float2(h0), f1 = __half22float2(h1);
        float4 v;
        v.x = f0.x + a.x; v.y = f0.y + a.y;
        v.z = f1.x + a.z; v.w = f1.y + a.w;
        *(float4*)&out[((size_t)b * NTOK + toks[row]) * DD + 4 * c4] = v;
    }
}

// ---------------- launch ----------------
extern "C" void kernel_launch(void* const* d_in, const int* in_sizes, int n_in,
                              void* d_out, int out_size)
{
    (void)in_sizes; (void)n_in; (void)out_size;
    const float* x    = (const float*)d_in[0];
    const int*   part = (const int*)d_in[1];   // int32 on device (JAX x64 disabled)
    const float* Wq_a = (const float*)d_in[2];
    const float* bq_a = (const float*)d_in[3];
    const float* Wk_a = (const float*)d_in[4];
    const float* bk_a = (const float*)d_in[5];
    const float* Wv_a = (const float*)d_in[6];
    const float* bv_a = (const float*)d_in[7];
    const float* Wo_a = (const float*)d_in[8];
    const float* bo_a = (const float*)d_in[9];
    const float* Wq_i = (const float*)d_in[10];
    const float* bq_i = (const float*)d_in[11];
    const float* Wk_i = (const float*)d_in[12];
    const float* bk_i = (const float*)d_in[13];
    const float* Wv_i = (const float*)d_in[14];
    const float* bv_i = (const float*)d_in[15];
    const float* Wo_i = (const float*)d_in[16];
    const float* bo_i = (const float*)d_in[17];
    float* out = (float*)d_out;

    const int smem_intra = SMEM_INTRA_BYTES;   // 54272 B
    const int smem_iatt  = SMEM_IATT_BYTES;    // 119808 B
    cudaFuncSetAttribute(intra_kernel, cudaFuncAttributeMaxDynamicSharedMemorySize, smem_intra);
    cudaFuncSetAttribute(inter_attn_mma, cudaFuncAttributeMaxDynamicSharedMemorySize, smem_iatt);

    prep_w_kernel<<<64, 256>>>(Wq_a, Wk_a, Wv_a, Wo_a, Wq_i, Wk_i, Wv_i, Wo_i);
    intra_kernel<<<BB * GG / 2, 256, smem_intra>>>(x, part, bq_a, bk_a, bv_a, bo_a);
    inter_attn_mma<<<64, 256, smem_iatt>>>(bq_i, bk_i, bv_i, bo_i);
    final_scatter_kernel<<<BB * GG, 256>>>(part, out);
}

// round 14
// speedup vs baseline: 1.0570x; 1.0570x over previous
#include <cuda_runtime.h>
#include <cuda_fp16.h>
#include <cstdint>

// Problem constants (fixed by the dataset)
constexpr int BB   = 16;     // batch
constexpr int NTOK = 16384;  // tokens
constexpr int DD   = 64;     // model dim (= dhf)
constexpr int GG   = 256;    // groups
constexpr int CC   = 64;     // tokens per group
constexpr int NH   = 4;      // heads
// SCALE = 4.0 multiplies scores; folded into Q at fp16 staging (exact: power of two)

#define PADH 72   // half smem row stride (144 B, ldmatrix conflict-free)
#define LDSF 68   // fp32 smem row stride (stash)

// intra smem layout (half indices)
#define XH_OFF 0
#define QH_OFF 4608
#define KH_OFF 9216
#define VH_OFF 13824
#define SMEM_INTRA_BYTES (4 * 4608 * 2)   // 36864 B -> 3 blocks/SM

// inter-attn smem layout (half indices)
#define PI_OFF  0
#define KI_OFF  18432
#define VI_OFF  36864
#define QI_OFF  55296
#define SMEM_IATT_BYTES ((55296 + 4608) * 2)   // 119808 B

// ---------------- scratch (no allocations allowed) ----------------
__device__ float  g_pooled[BB * GG * DD];          // 1 MiB
__device__ float  g_inter[BB * GG * DD];           // 1 MiB
__device__ __half g_intra[BB * GG * CC * DD];      // 32 MiB (fp16 intra result)
// pre-packed fp16 weight fragments: [mat][(ntg*4+kt)*64 + 2*lane + j]
// mats: 0=Wq_a 1=Wk_a 2=Wv_a 3=Wo_a 4=Wq_i 5=Wk_i 6=Wv_i 7=Wo_i
__device__ uint32_t g_wfrag[8][2048];              // 64 KiB

// ---------------- mma / ldmatrix helpers ----------------
__device__ __forceinline__ void ldsm_x4(uint32_t& r0, uint32_t& r1, uint32_t& r2, uint32_t& r3, uint32_t a) {
    asm volatile("ldmatrix.sync.aligned.m8n8.x4.shared.b16 {%0,%1,%2,%3}, [%4];"
        : "=r"(r0), "=r"(r1), "=r"(r2), "=r"(r3) : "r"(a));
}
__device__ __forceinline__ void ldsm_x4t(uint32_t& r0, uint32_t& r1, uint32_t& r2, uint32_t& r3, uint32_t a) {
    asm volatile("ldmatrix.sync.aligned.m8n8.x4.trans.shared.b16 {%0,%1,%2,%3}, [%4];"
        : "=r"(r0), "=r"(r1), "=r"(r2), "=r"(r3) : "r"(a));
}
__device__ __forceinline__ void mma16(float c[4],
    uint32_t a0, uint32_t a1, uint32_t a2, uint32_t a3, uint32_t b0, uint32_t b1) {
    asm volatile("mma.sync.aligned.m16n8k16.row.col.f32.f16.f16.f32 "
        "{%0,%1,%2,%3}, {%4,%5,%6,%7}, {%8,%9}, {%0,%1,%2,%3};"
        : "+f"(c[0]), "+f"(c[1]), "+f"(c[2]), "+f"(c[3])
        : "r"(a0), "r"(a1), "r"(a2), "r"(a3), "r"(b0), "r"(b1));
}
__device__ __forceinline__ uint32_t packh2(float a, float b) {
    uint32_t u;
    asm("cvt.rn.f16x2.f32 %0, %1, %2;" : "=r"(u) : "f"(b), "f"(a));
    return u;
}

// ---------------- Kernel 0: pack weights into B-fragment layout ----------------
__global__ __launch_bounds__(256) void prep_w_kernel(
    const float* __restrict__ Wqa, const float* __restrict__ Wka,
    const float* __restrict__ Wva, const float* __restrict__ Woa,
    const float* __restrict__ Wqi, const float* __restrict__ Wki,
    const float* __restrict__ Wvi, const float* __restrict__ Woi)
{
    const int idx = blockIdx.x * 256 + threadIdx.x;   // 0..16383
    const int mat = idx >> 11;
    const int t   = idx & 2047;
    const int lane2 = t & 63;        // 2*lane + j
    const int j = lane2 & 1, l = lane2 >> 1;
    const int tile = t >> 6;         // ntg*4 + kt
    const int kt = tile & 3, ntg = tile >> 2;
    const float* W =
        (mat == 0) ? Wqa : (mat == 1) ? Wka : (mat == 2) ? Wva : (mat == 3) ? Woa :
        (mat == 4) ? Wqi : (mat == 5) ? Wki : (mat == 6) ? Wvi : Woi;
    const int row = 8 * ntg + (l >> 2);
    const int col = 16 * kt + 8 * j + 2 * (l & 3);
    g_wfrag[mat][t] = packh2(W[row * 64 + col], W[row * 64 + col + 1]);
}

// ---------------- Kernel 1: intra-group MHA (fp16 mma, global weight frags) ----------------
// grid = 4096 (b*256+g), 256 threads = 8 warps, dyn smem = 36864 B
__global__ __launch_bounds__(256, 3) void intra_kernel(
    const float* __restrict__ x, const int* __restrict__ part,
    const float* __restrict__ bq, const float* __restrict__ bk,
    const float* __restrict__ bv, const float* __restrict__ bo)
{
    extern __shared__ __half hsm[];
    float* stash = (float*)(hsm + QH_OFF);   // 64 x LDSF fp32 overlay (dead Q/K)
    float* tmp   = (float*)(hsm + VH_OFF);   // 256 fp32 overlay (dead V, after attention)

    const int tid = threadIdx.x;
    const int bb = blockIdx.x >> 8;
    const int g  = blockIdx.x & 255;
    const int* pg = part + (size_t)g * CC;
    const float* xb = x + (size_t)bb * NTOK * DD;

    const int lane = tid & 31, w = tid >> 5;
    const int mt = w & 3, nq = w >> 2;
    const int r  = lane >> 2, cc = lane & 3;
    const int ln = lane & 7, sel = lane >> 3;
    const int offA   = (ln + 8 * (sel & 1)) * PADH + 8 * (sel >> 1);   // A x4
    const int offBK  = (ln + 8 * (sel >> 1)) * PADH + 8 * (sel & 1);   // B x4: 2 n-tiles, k16
    const int offB4t = (lane & 15) * PADH + 8 * (lane >> 4);           // B x4 trans: 2 n-halves

    const uint32_t sbase = (uint32_t)__cvta_generic_to_shared(hsm);
    const int row0 = 16 * mt + r;

    // ---- gather x (fp32 -> half) ----
#pragma unroll
    for (int k = 0; k < 4; ++k) {
        int f = tid + 256 * k;
        int row = f >> 4, c4 = f & 15;
        int tok = pg[row];
        float4 v = ((const float4*)(xb + (size_t)tok * DD))[c4];
        __half* d = hsm + XH_OFF + row * PADH + 4 * c4;
        *(half2*)(d)     = __floats2half2_rn(v.x, v.y);
        *(half2*)(d + 2) = __floats2half2_rn(v.z, v.w);
    }
    __syncthreads();

    // ---- A fragments of xs: shared by Q, K, V projections ----
    uint32_t xa[4][4];
#pragma unroll
    for (int kt = 0; kt < 4; ++kt)
        ldsm_x4(xa[kt][0], xa[kt][1], xa[kt][2], xa[kt][3],
                sbase + 2 * (XH_OFF + 16 * mt * PADH + 16 * kt + offA));

    auto projG = [&](int mat, const float* __restrict__ bias, int Doff, float scl) {
        const uint2* wf = (const uint2*)g_wfrag[mat];
        float acc[4][4] = {};
#pragma unroll
        for (int nt = 0; nt < 4; ++nt) {
            const int ntg = 4 * nq + nt;
#pragma unroll
            for (int kt = 0; kt < 4; ++kt) {
                uint2 f = wf[(ntg * 4 + kt) * 32 + lane];
                mma16(acc[nt], xa[kt][0], xa[kt][1], xa[kt][2], xa[kt][3], f.x, f.y);
            }
        }
#pragma unroll
        for (int nt = 0; nt < 4; ++nt) {
            const int n0 = 32 * nq + 8 * nt;
            float b0v = bias[n0 + 2 * cc], b1v = bias[n0 + 2 * cc + 1];
            *(half2*)(hsm + Doff + row0 * PADH + n0 + 2 * cc) =
                __floats2half2_rn((acc[nt][0] + b0v) * scl, (acc[nt][1] + b1v) * scl);
            *(half2*)(hsm + Doff + (row0 + 8) * PADH + n0 + 2 * cc) =
                __floats2half2_rn((acc[nt][2] + b0v) * scl, (acc[nt][3] + b1v) * scl);
        }
    };

    projG(0, bq, QH_OFF, 4.0f);
    projG(1, bk, KH_OFF, 1.0f);
    projG(2, bv, VH_OFF, 1.0f);
    __syncthreads();

    // ---- attention, register-resident ----
    {
        const int hsel = w >> 2;
        const int arow = 16 * mt;
#pragma unroll
        for (int hp = 0; hp < 2; ++hp) {
            const int h = 2 * hp + hsel;
            const int hq = 16 * h;
            uint32_t a0, a1, a2, a3;
            ldsm_x4(a0, a1, a2, a3, sbase + 2 * (QH_OFF + arow * PADH + hq + offA));
            float s[8][4];
#pragma unroll
            for (int ntp = 0; ntp < 4; ++ntp) {
                uint32_t b0, b1, b2, b3;
                ldsm_x4(b0, b1, b2, b3, sbase + 2 * (KH_OFF + 16 * ntp * PADH + hq + offBK));
                s[2*ntp][0] = s[2*ntp][1] = s[2*ntp][2] = s[2*ntp][3] = 0.f;
                s[2*ntp+1][0] = s[2*ntp+1][1] = s[2*ntp+1][2] = s[2*ntp+1][3] = 0.f;
                mma16(s[2*ntp],   a0, a1, a2, a3, b0, b1);
                mma16(s[2*ntp+1], a0, a1, a2, a3, b2, b3);
            }
            float mx0 = -1e30f, mx1 = -1e30f;
#pragma unroll
            for (int nt = 0; nt < 8; ++nt) {
                mx0 = fmaxf(mx0, fmaxf(s[nt][0], s[nt][1]));
                mx1 = fmaxf(mx1, fmaxf(s[nt][2], s[nt][3]));
            }
            mx0 = fmaxf(mx0, __shfl_xor_sync(0xffffffffu, mx0, 1));
            mx0 = fmaxf(mx0, __shfl_xor_sync(0xffffffffu, mx0, 2));
            mx1 = fmaxf(mx1, __shfl_xor_sync(0xffffffffu, mx1, 1));
            mx1 = fmaxf(mx1, __shfl_xor_sync(0xffffffffu, mx1, 2));
            float sum0 = 0.f, sum1 = 0.f;
#pragma unroll
            for (int nt = 0; nt < 8; ++nt) {
                s[nt][0] = __expf(s[nt][0] - mx0); sum0 += s[nt][0];
                s[nt][1] = __expf(s[nt][1] - mx0); sum0 += s[nt][1];
                s[nt][2] = __expf(s[nt][2] - mx1); sum1 += s[nt][2];
                s[nt][3] = __expf(s[nt][3] - mx1); sum1 += s[nt][3];
            }
            sum0 += __shfl_xor_sync(0xffffffffu, sum0, 1);
            sum0 += __shfl_xor_sync(0xffffffffu, sum0, 2);
            sum1 += __shfl_xor_sync(0xffffffffu, sum1, 1);
            sum1 += __shfl_xor_sync(0xffffffffu, sum1, 2);
            const float inv0 = 1.f / sum0, inv1 = 1.f / sum1;
            float o[2][4] = {};
#pragma unroll
            for (int kc = 0; kc < 4; ++kc) {
                uint32_t pa0 = packh2(s[2*kc][0] * inv0, s[2*kc][1] * inv0);
                uint32_t pa1 = packh2(s[2*kc][2] * inv1, s[2*kc][3] * inv1);
                uint32_t pa2 = packh2(s[2*kc+1][0] * inv0, s[2*kc+1][1] * inv0);
                uint32_t pa3 = packh2(s[2*kc+1][2] * inv1, s[2*kc+1][3] * inv1);
                uint32_t b0, b1, b2, b3;
                ldsm_x4t(b0, b1, b2, b3, sbase + 2 * (VH_OFF + 16 * kc * PADH + hq + offB4t));
                mma16(o[0], pa0, pa1, pa2, pa3, b0, b1);
                mma16(o[1], pa0, pa1, pa2, pa3, b2, b3);
            }
#pragma unroll
            for (int nt2 = 0; nt2 < 2; ++nt2) {
                const int n0 = hq + 8 * nt2 + 2 * cc;
                *(half2*)(hsm + XH_OFF + (arow + r) * PADH + n0) =
                    __floats2half2_rn(o[nt2][0], o[nt2][1]);
                *(half2*)(hsm + XH_OFF + (arow + r + 8) * PADH + n0) =
                    __floats2half2_rn(o[nt2][2], o[nt2][3]);
            }
        }
    }
    __syncthreads();

    // ---- O projection (+bias) -> fp16 g_intra (coalesced) + fp32 stash ----
    {
#pragma unroll
        for (int kt = 0; kt < 4; ++kt)
            ldsm_x4(xa[kt][0], xa[kt][1], xa[kt][2], xa[kt][3],
                    sbase + 2 * (XH_OFF + 16 * mt * PADH + 16 * kt + offA));
        const uint2* wf = (const uint2*)g_wfrag[3];
        float acc[4][4] = {};
#pragma unroll
        for (int nt = 0; nt < 4; ++nt) {
            const int ntg = 4 * nq + nt;
#pragma unroll
            for (int kt = 0; kt < 4; ++kt) {
                uint2 f = wf[(ntg * 4 + kt) * 32 + lane];
                mma16(acc[nt], xa[kt][0], xa[kt][1], xa[kt][2], xa[kt][3], f.x, f.y);
            }
        }
        __half* dI = g_intra + ((size_t)(bb * GG + g) * CC) * DD;
#pragma unroll
        for (int nt = 0; nt < 4; ++nt) {
            const int n0 = 32 * nq + 8 * nt;
            float b0v = bo[n0 + 2 * cc], b1v = bo[n0 + 2 * cc + 1];
            float v0 = acc[nt][0] + b0v, v1 = acc[nt][1] + b1v;
            float v2 = acc[nt][2] + b0v, v3 = acc[nt][3] + b1v;
            *(half2*)(dI + row0 * DD + n0 + 2 * cc)       = __floats2half2_rn(v0, v1);
            *(half2*)(dI + (row0 + 8) * DD + n0 + 2 * cc) = __floats2half2_rn(v2, v3);
            *(float2*)&stash[row0 * LDSF + n0 + 2 * cc]       = make_float2(v0, v1);
            *(float2*)&stash[(row0 + 8) * LDSF + n0 + 2 * cc] = make_float2(v2, v3);
        }
    }
    __syncthreads();

    // ---- pooled max (256 threads: 4 quarters x 64 cols, then tree) ----
    {
        const int col = tid & 63, q = tid >> 6;
        const float* sp = stash + (16 * q) * LDSF + col;
        float m = sp[0];
#pragma unroll
        for (int i = 1; i < 16; ++i) m = fmaxf(m, sp[i * LDSF]);
        tmp[(q << 6) + col] = m;
    }
    __syncthreads();
    if (tid < 64) {
        float m = fmaxf(fmaxf(tmp[tid], tmp[64 + tid]),
                        fmaxf(tmp[128 + tid], tmp[192 + tid]));
        g_pooled[((size_t)bb * GG + g) * DD + tid] = m;
    }
}

// ---------------- Kernel 2: fused inter QKV + flash attention + O-proj ----------------
// grid = 64 (b = blk>>2, qchunk = blk&3), 256 threads, dyn smem = 119808 B
__global__ __launch_bounds__(256) void inter_attn_mma(
    const float* __restrict__ bq, const float* __restrict__ bk,
    const float* __restrict__ bv, const float* __restrict__ bo)
{
    extern __shared__ __half hsm[];
    const int tid = threadIdx.x;
    const int b  = blockIdx.x >> 2;
    const int qc = blockIdx.x & 3;

    const int lane = tid & 31, w = tid >> 5;
    const int mt = w & 3, nq = w >> 2;
    const int r  = lane >> 2, cc = lane & 3;
    const int ln = lane & 7, sel = lane >> 3;
    const int offA   = (ln + 8 * (sel & 1)) * PADH + 8 * (sel >> 1);
    const int offBK  = (ln + 8 * (sel >> 1)) * PADH + 8 * (sel & 1);
    const int offB4t = (lane & 15) * PADH + 8 * (lane >> 4);
    const uint32_t sbase = (uint32_t)__cvta_generic_to_shared(hsm);

    const float* pb = g_pooled + (size_t)b * GG * DD;

    // ---- stage pooled (256 x 64) as fp16 ----
#pragma unroll
    for (int k = 0; k < 16; ++k) {
        int f = tid + 256 * k;
        int row = f >> 4, c4 = f & 15;
        float4 v = ((const float4*)(pb + row * 64))[c4];
        __half* d = hsm + PI_OFF + row * PADH + 4 * c4;
        *(half2*)(d)     = __floats2half2_rn(v.x, v.y);
        *(half2*)(d + 2) = __floats2half2_rn(v.z, v.w);
    }
    __syncthreads();

    // ---- K, V projections over all 256 rows; Q over own 64 rows ----
    {
        const uint2* wfK = (const uint2*)g_wfrag[5];
        const uint2* wfV = (const uint2*)g_wfrag[6];
#pragma unroll
        for (int hf = 0; hf < 2; ++hf) {
            const int rt = w + 8 * hf;
            uint32_t pa[4][4];
#pragma unroll
            for (int kt = 0; kt < 4; ++kt)
                ldsm_x4(pa[kt][0], pa[kt][1], pa[kt][2], pa[kt][3],
                        sbase + 2 * (PI_OFF + 16 * rt * PADH + 16 * kt + offA));
            const int rr0 = 16 * rt + r;
#pragma unroll
            for (int ng = 0; ng < 8; ++ng) {
                float ak[4] = {}, av[4] = {};
#pragma unroll
                for (int kt = 0; kt < 4; ++kt) {
                    uint2 fk = wfK[(ng * 4 + kt) * 32 + lane];
                    uint2 fv = wfV[(ng * 4 + kt) * 32 + lane];
                    mma16(ak, pa[kt][0], pa[kt][1], pa[kt][2], pa[kt][3], fk.x, fk.y);
                    mma16(av, pa[kt][0], pa[kt][1], pa[kt][2], pa[kt][3], fv.x, fv.y);
                }
                const int n0 = 8 * ng;
                float bk0 = bk[n0 + 2 * cc], bk1 = bk[n0 + 2 * cc + 1];
                float bv0 = bv[n0 + 2 * cc], bv1 = bv[n0 + 2 * cc + 1];
                *(half2*)(hsm + KI_OFF + rr0 * PADH + n0 + 2 * cc) =
                    __floats2half2_rn(ak[0] + bk0, ak[1] + bk1);
                *(half2*)(hsm + KI_OFF + (rr0 + 8) * PADH + n0 + 2 * cc) =
                    __floats2half2_rn(ak[2] + bk0, ak[3] + bk1);
                *(half2*)(hsm + VI_OFF + rr0 * PADH + n0 + 2 * cc) =
                    __floats2half2_rn(av[0] + bv0, av[1] + bv1);
                *(half2*)(hsm + VI_OFF + (rr0 + 8) * PADH + n0 + 2 * cc) =
                    __floats2half2_rn(av[2] + bv0, av[3] + bv1);
            }
        }
        const uint2* wfQ = (const uint2*)g_wfrag[4];
        const int qt = 4 * qc + mt;
        uint32_t pa[4][4];
#pragma unroll
        for (int kt = 0; kt < 4; ++kt)
            ldsm_x4(pa[kt][0], pa[kt][1], pa[kt][2], pa[kt][3],
                    sbase + 2 * (PI_OFF + 16 * qt * PADH + 16 * kt + offA));
        float acc[4][4] = {};
#pragma unroll
        for (int nt = 0; nt < 4; ++nt) {
            const int ntg = 4 * nq + nt;
#pragma unroll
            for (int kt = 0; kt < 4; ++kt) {
                uint2 f = wfQ[(ntg * 4 + kt) * 32 + lane];
                mma16(acc[nt], pa[kt][0], pa[kt][1], pa[kt][2], pa[kt][3], f.x, f.y);
            }
        }
        const int lrow0 = 16 * mt + r;
#pragma unroll
        for (int nt = 0; nt < 4; ++nt) {
            const int n0 = 32 * nq + 8 * nt;
            float b0v = bq[n0 + 2 * cc], b1v = bq[n0 + 2 * cc + 1];
            *(half2*)(hsm + QI_OFF + lrow0 * PADH + n0 + 2 * cc) =
                __floats2half2_rn((acc[nt][0] + b0v) * 4.f, (acc[nt][1] + b1v) * 4.f);
            *(half2*)(hsm + QI_OFF + (lrow0 + 8) * PADH + n0 + 2 * cc) =
                __floats2half2_rn((acc[nt][2] + b0v) * 4.f, (acc[nt][3] + b1v) * 4.f);
        }
    }
    __syncthreads();

    // ---- flash attention: warp = (mt rows, hsel head-pair), 256 keys in 2 chunks ----
    {
        const int hsel = w >> 2;
        const int arow = 16 * mt;
#pragma unroll 1
        for (int hp = 0; hp < 2; ++hp) {
            const int h = 2 * hp + hsel;
            const int hq = 16 * h;
            uint32_t a0, a1, a2, a3;
            ldsm_x4(a0, a1, a2, a3, sbase + 2 * (QI_OFF + arow * PADH + hq + offA));
            float o[2][4] = {};
            float m0 = -1e30f, m1 = -1e30f, l0 = 0.f, l1 = 0.f;
#pragma unroll 1
            for (int c = 0; c < 2; ++c) {
                float s[16][4];
#pragma unroll
                for (int ntp = 0; ntp < 8; ++ntp) {
                    uint32_t b0, b1, b2, b3;
                    ldsm_x4(b0, b1, b2, b3,
                        sbase + 2 * (KI_OFF + (128 * c + 16 * ntp) * PADH + hq + offBK));
                    s[2*ntp][0] = s[2*ntp][1] = s[2*ntp][2] = s[2*ntp][3] = 0.f;
                    s[2*ntp+1][0] = s[2*ntp+1][1] = s[2*ntp+1][2] = s[2*ntp+1][3] = 0.f;
                    mma16(s[2*ntp],   a0, a1, a2, a3, b0, b1);
                    mma16(s[2*ntp+1], a0, a1, a2, a3, b2, b3);
                }
                float cm0 = -1e30f, cm1 = -1e30f;
#pragma unroll
                for (int nt = 0; nt < 16; ++nt) {
                    cm0 = fmaxf(cm0, fmaxf(s[nt][0], s[nt][1]));
                    cm1 = fmaxf(cm1, fmaxf(s[nt][2], s[nt][3]));
                }
                cm0 = fmaxf(cm0, __shfl_xor_sync(0xffffffffu, cm0, 1));
                cm0 = fmaxf(cm0, __shfl_xor_sync(0xffffffffu, cm0, 2));
                cm1 = fmaxf(cm1, __shfl_xor_sync(0xffffffffu, cm1, 1));
                cm1 = fmaxf(cm1, __shfl_xor_sync(0xffffffffu, cm1, 2));
                float nm0 = fmaxf(m0, cm0), nm1 = fmaxf(m1, cm1);
                float sc0 = __expf(m0 - nm0), sc1 = __expf(m1 - nm1);
                l0 *= sc0; l1 *= sc1;
#pragma unroll
                for (int nt2 = 0; nt2 < 2; ++nt2) {
                    o[nt2][0] *= sc0; o[nt2][1] *= sc0;
                    o[nt2][2] *= sc1; o[nt2][3] *= sc1;
                }
                float cl0 = 0.f, cl1 = 0.f;
#pragma unroll
                for (int nt = 0; nt < 16; ++nt) {
                    s[nt][0] = __expf(s[nt][0] - nm0); cl0 += s[nt][0];
                    s[nt][1] = __expf(s[nt][1] - nm0); cl0 += s[nt][1];
                    s[nt][2] = __expf(s[nt][2] - nm1); cl1 += s[nt][2];
                    s[nt][3] = __expf(s[nt][3] - nm1); cl1 += s[nt][3];
                }
                cl0 += __shfl_xor_sync(0xffffffffu, cl0, 1);
                cl0 += __shfl_xor_sync(0xffffffffu, cl0, 2);
                cl1 += __shfl_xor_sync(0xffffffffu, cl1, 1);
                cl1 += __shfl_xor_sync(0xffffffffu, cl1, 2);
                l0 += cl0; l1 += cl1;
                m0 = nm0; m1 = nm1;
#pragma unroll
                for (int kc = 0; kc < 8; ++kc) {
                    uint32_t pa0 = packh2(s[2*kc][0], s[2*kc][1]);
                    uint32_t pa1 = packh2(s[2*kc][2], s[2*kc][3]);
                    uint32_t pa2 = packh2(s[2*kc+1][0], s[2*kc+1][1]);
                    uint32_t pa3 = packh2(s[2*kc+1][2], s[2*kc+1][3]);
                    uint32_t b0, b1, b2, b3;
                    ldsm_x4t(b0, b1, b2, b3,
                        sbase + 2 * (VI_OFF + (128 * c + 16 * kc) * PADH + hq + offB4t));
                    mma16(o[0], pa0, pa1, pa2, pa3, b0, b1);
                    mma16(o[1], pa0, pa1, pa2, pa3, b2, b3);
                }
            }
            const float inv0 = 1.f / l0, inv1 = 1.f / l1;
#pragma unroll
            for (int nt2 = 0; nt2 < 2; ++nt2) {
                const int n0 = hq + 8 * nt2 + 2 * cc;
                *(half2*)(hsm + QI_OFF + (arow + r) * PADH + n0) =
                    __floats2half2_rn(o[nt2][0] * inv0, o[nt2][1] * inv0);
                *(half2*)(hsm + QI_OFF + (arow + r + 8) * PADH + n0) =
                    __floats2half2_rn(o[nt2][2] * inv1, o[nt2][3] * inv1);
            }
        }
    }
    __syncthreads();

    // ---- O projection (+bias) -> g_inter ----
    {
        uint32_t xa[4][4];
#pragma unroll
        for (int kt = 0; kt < 4; ++kt)
            ldsm_x4(xa[kt][0], xa[kt][1], xa[kt][2], xa[kt][3],
                    sbase + 2 * (QI_OFF + 16 * mt * PADH + 16 * kt + offA));
        const uint2* wf = (const uint2*)g_wfrag[7];
        float acc[4][4] = {};
#pragma unroll
        for (int nt = 0; nt < 4; ++nt) {
            const int ntg = 4 * nq + nt;
#pragma unroll
            for (int kt = 0; kt < 4; ++kt) {
                uint2 f = wf[(ntg * 4 + kt) * 32 + lane];
                mma16(acc[nt], xa[kt][0], xa[kt][1], xa[kt][2], xa[kt][3], f.x, f.y);
            }
        }
        const int row0 = 16 * mt + r;
        float* dst = g_inter + ((size_t)b * GG + qc * 64) * DD;
#pragma unroll
        for (int nt = 0; nt < 4; ++nt) {
            const int n0 = 32 * nq + 8 * nt;
            float b0v = bo[n0 + 2 * cc], b1v = bo[n0 + 2 * cc + 1];
            *(float2*)(dst + row0 * DD + n0 + 2 * cc) =
                make_float2(acc[nt][0] + b0v, acc[nt][1] + b1v);
            *(float2*)(dst + (row0 + 8) * DD + n0 + 2 * cc) =
                make_float2(acc[nt][2] + b0v, acc[nt][3] + b1v);
        }
    }
}

// ---------------- Kernel 3: final add + scatter (only writer of out) ----------------
__global__ __launch_bounds__(256) void final_scatter_kernel(
    const int* __restrict__ part, float* __restrict__ out)
{
    __shared__ __align__(16) float iv[64];
    __shared__ int toks[64];
    const int tid = threadIdx.x;
    const int b = blockIdx.x >> 8;
    const int g = blockIdx.x & 255;
    if (tid < 64) iv[tid] = g_inter[((size_t)b * GG + g) * DD + tid];
    else if (tid < 128) toks[tid - 64] = part[(size_t)g * CC + (tid - 64)];
    __syncthreads();
    const __half* src = g_intra + ((size_t)(b * GG + g) * CC) * DD;
#pragma unroll
    for (int k = 0; k < 4; ++k) {
        int f = tid + 256 * k;
        int row = f >> 4, c4 = f & 15;
        half2 h0 = *(const half2*)(src + row * DD + 4 * c4);
        half2 h1 = *(const half2*)(src + row * DD + 4 * c4 + 2);
        float4 a = *(const float4*)&iv[4 * c4];
        float2 f0 = __half22float2(h0), f1 = __half22float2(h1);
        float4 v;
        v.x = f0.x + a.x; v.y = f0.y + a.y;
        v.z = f1.x + a.z; v.w = f1.y + a.w;
        *(float4*)&out[((size_t)b * NTOK + toks[row]) * DD + 4 * c4] = v;
    }
}

// ---------------- launch ----------------
extern "C" void kernel_launch(void* const* d_in, const int* in_sizes, int n_in,
                              void* d_out, int out_size)
{
    (void)in_sizes; (void)n_in; (void)out_size;
    const float* x    = (const float*)d_in[0];
    const int*   part = (const int*)d_in[1];   // int32 on device (JAX x64 disabled)
    const float* Wq_a = (const float*)d_in[2];
    const float* bq_a = (const float*)d_in[3];
    const float* Wk_a = (const float*)d_in[4];
    const float* bk_a = (const float*)d_in[5];
    const float* Wv_a = (const float*)d_in[6];
    const float* bv_a = (const float*)d_in[7];
    const float* Wo_a = (const float*)d_in[8];
    const float* bo_a = (const float*)d_in[9];
    const float* Wq_i = (const float*)d_in[10];
    const float* bq_i = (const float*)d_in[11];
    const float* Wk_i = (const float*)d_in[12];
    const float* bk_i = (const float*)d_in[13];
    const float* Wv_i = (const float*)d_in[14];
    const float* bv_i = (const float*)d_in[15];
    const float* Wo_i = (const float*)d_in[16];
    const float* bo_i = (const float*)d_in[17];
    float* out = (float*)d_out;

    const int smem_intra = SMEM_INTRA_BYTES;   // 36864 B
    const int smem_iatt  = SMEM_IATT_BYTES;    // 119808 B
    cudaFuncSetAttribute(intra_kernel, cudaFuncAttributeMaxDynamicSharedMemorySize, smem_intra);
    cudaFuncSetAttribute(inter_attn_mma, cudaFuncAttributeMaxDynamicSharedMemorySize, smem_iatt);

    prep_w_kernel<<<64, 256>>>(Wq_a, Wk_a, Wv_a, Wo_a, Wq_i, Wk_i, Wv_i, Wo_i);
    intra_kernel<<<BB * GG, 256, smem_intra>>>(x, part, bq_a, bk_a, bv_a, bo_a);
    inter_attn_mma<<<64, 256, smem_iatt>>>(bq_i, bk_i, bv_i, bo_i);
    final_scatter_kernel<<<BB * GG, 256>>>(part, out);
}